// round 7
// baseline (speedup 1.0000x reference)
#include <cuda_runtime.h>
#include <cstdint>

// SpatialGradientLoss3D = mean |sobel3d(pred - target)| over 3 axes.
// R7: R6 (cp.async 4-stage ring, depth-3, f32x2 math, single launch) +
//   (a) incremental z-accumulation: pending-output accumulators instead of
//       3-slot ss/ds/sd ring  (36 -> 24 state regs)
//   (b) row-streamed plane consume (lower peak temporaries)
//   (c) __launch_bounds__(256,4) -> 32 warps/SM
// Shapes fixed: (B=4, C=4, D=64, H=128, W=128), fp32, out = 1 float.

#define D_DIM 64
#define H_DIM 128
#define W_DIM 128
#define HW    (H_DIM * W_DIM)
#define BC_DIM 16
#define TH 8
#define PR (TH + 2)
#define ZC 16
#define NP (ZC + 2)             // 18 planes touched
#define NSTAGE 4
#define PLANE_F4 (2 * PR * 32)  // 640 float4 per ring stage (P then T)
#define STAGE_BYTES (PLANE_F4 * 16)
#define NBLK (16 * 16 * 4)      // 1024

typedef unsigned long long F2;  // packed f32x2

__device__ __forceinline__ F2 PACK2(float lo, float hi) {
    F2 r; asm("mov.b64 %0,{%1,%2};" : "=l"(r) : "f"(lo), "f"(hi)); return r;
}
__device__ __forceinline__ void UNPACK2(F2 v, float& lo, float& hi) {
    asm("mov.b64 {%0,%1},%2;" : "=f"(lo), "=f"(hi) : "l"(v));
}
__device__ __forceinline__ F2 ADD2(F2 a, F2 b) {
    F2 r; asm("add.rn.f32x2 %0,%1,%2;" : "=l"(r) : "l"(a), "l"(b)); return r;
}
__device__ __forceinline__ F2 SUB2(F2 a, F2 b) {
    F2 r; asm("sub.rn.f32x2 %0,%1,%2;" : "=l"(r) : "l"(a), "l"(b)); return r;
}
__device__ __forceinline__ F2 FMA2(F2 a, F2 b, F2 c) {
    F2 r; asm("fma.rn.f32x2 %0,%1,%2,%3;" : "=l"(r) : "l"(a), "l"(b), "l"(c)); return r;
}
__device__ __forceinline__ F2 ABS2(F2 a) { return a & 0x7FFFFFFF7FFFFFFFULL; }

__device__ __forceinline__ void cpasync16(uint32_t dst, const float* src, int sz) {
    asm volatile("cp.async.cg.shared.global [%0], [%1], 16, %2;\n"
                 :: "r"(dst), "l"(src), "r"(sz) : "memory");
}
__device__ __forceinline__ void cp_commit() {
    asm volatile("cp.async.commit_group;\n" ::: "memory");
}
__device__ __forceinline__ void cp_wait2() {
    asm volatile("cp.async.wait_group 2;\n" ::: "memory");
}

__shared__ float4 sbuf[NSTAGE][PLANE_F4];
__shared__ float wsum_sm[8];

__device__ float g_partials[NBLK];
__device__ unsigned g_count = 0;

// Consume plane from ring stage STG: produce S (h-smooth of ws),
// D (h-deriv of ws), W (h-smooth of wd), each F2[2]. Row-streamed.
template<int STG>
__device__ __forceinline__ void plane_consume(int warp, int lane,
                                              F2* S, F2* D, F2* W,
                                              F2 TWO2, bool l0, bool l31) {
    const ulonglong2* sb = reinterpret_cast<const ulonglong2*>(&sbuf[STG][0]);
    F2 Dneg[2];
#pragma unroll
    for (int dr = 0; dr < 3; ++dr) {
        ulonglong2 pv = sb[(warp + dr) * 32 + lane];
        ulonglong2 tv = sb[PR * 32 + (warp + dr) * 32 + lane];
        F2 e01 = SUB2(pv.x, tv.x);
        F2 e23 = SUB2(pv.y, tv.y);
        float e0, e1, e2, e3;
        UNPACK2(e01, e0, e1);
        UNPACK2(e23, e2, e3);
        float eL = __shfl_up_sync(0xffffffffu, e3, 1);
        float eR = __shfl_down_sync(0xffffffffu, e0, 1);
        if (l0)  eL = 0.f;
        if (l31) eR = 0.f;
        F2 pm  = PACK2(eL, e0);
        F2 p12 = PACK2(e1, e2);
        F2 pr  = PACK2(e3, eR);
        F2 ws0 = ADD2(FMA2(e01, TWO2, pm),  p12);
        F2 ws1 = ADD2(FMA2(e23, TWO2, p12), pr);
        F2 wd0 = SUB2(p12, pm);
        F2 wd1 = SUB2(pr, p12);
        if (dr == 0) {
            S[0] = ws0;  S[1] = ws1;
            Dneg[0] = ws0; Dneg[1] = ws1;
            W[0] = wd0;  W[1] = wd1;
        } else if (dr == 1) {
            S[0] = FMA2(ws0, TWO2, S[0]);
            S[1] = FMA2(ws1, TWO2, S[1]);
            W[0] = FMA2(wd0, TWO2, W[0]);
            W[1] = FMA2(wd1, TWO2, W[1]);
        } else {
            S[0] = ADD2(S[0], ws0);
            S[1] = ADD2(S[1], ws1);
            D[0] = SUB2(ws0, Dneg[0]);
            D[1] = SUB2(ws1, Dneg[1]);
            W[0] = ADD2(W[0], wd0);
            W[1] = ADD2(W[1], wd1);
        }
    }
}

__global__ __launch_bounds__(256, 4)
void sg3d_loss_kernel(const float* __restrict__ pred,
                      const float* __restrict__ tgt,
                      float* __restrict__ out) {
    const int tid  = threadIdx.x;
    const int lane = tid & 31;
    const int warp = tid >> 5;
    const bool l0  = (lane == 0);
    const bool l31 = (lane == 31);

    const int h0 = blockIdx.x * TH;
    const int bc = blockIdx.y;
    const int z0 = blockIdx.z * ZC;
    const int bid = blockIdx.x + (blockIdx.y << 4) + (blockIdx.z << 8);

    const size_t base = (size_t)bc * D_DIM * HW;
    const float* P = pred + base;
    const float* T = tgt + base;

    uint32_t smem_base;
    asm("{ .reg .u64 t; cvta.to.shared.u64 t, %1; cvt.u32.u64 %0, t; }"
        : "=r"(smem_base) : "l"((const void*)&sbuf[0][0]));

    // per-slot cp.async params (slot k covers idx = tid + 256k)
    const float* gp[3];
    uint32_t saddr[3];
    int rowok[3], active[3];
#pragma unroll
    for (int k = 0; k < 3; ++k) {
        int idx = tid + 256 * k;
        active[k] = idx < PLANE_F4;
        int a   = idx >= PR * 32;
        int rel = idx - a * PR * 32;
        int row = rel >> 5;
        int c4  = rel & 31;
        int gh  = h0 - 1 + row;
        rowok[k] = (unsigned)gh < (unsigned)H_DIM;
        int soff = (rowok[k] ? gh : 0) * W_DIM + c4 * 4;
        gp[k] = (a ? T : P) + soff;
        saddr[k] = smem_base + (uint32_t)idx * 16u;
    }

#define ISSUE_PLANE(J, STAGE)                                                 \
    do {                                                                      \
        int gz_ = z0 - 1 + (J);                                               \
        int zok_ = (unsigned)gz_ < (unsigned)D_DIM;                           \
        int gzc_ = zok_ ? gz_ : 0;                                            \
        _Pragma("unroll")                                                     \
        for (int k = 0; k < 3; ++k) {                                         \
            if (active[k]) {                                                  \
                int sz_ = (rowok[k] & zok_) ? 16 : 0;                         \
                cpasync16(saddr[k] + (STAGE) * STAGE_BYTES,                   \
                          gp[k] + (size_t)gzc_ * HW, sz_);                    \
            }                                                                 \
        }                                                                     \
    } while (0)

    const F2 TWO2 = 0x4000000040000000ULL;

    // incremental z-state
    F2 pend_h0[2] = {0, 0}, pend_h1[2] = {0, 0};
    F2 pend_w0[2] = {0, 0}, pend_w1[2] = {0, 0};
    F2 s_old[2]   = {0, 0}, s_new[2]   = {0, 0};
    F2 acc[2] = {0, 0};

    // prologue: planes 0,1,2 -> stages 0,1,2
    ISSUE_PLANE(0, 0); cp_commit();
    ISSUE_PLANE(1, 1); cp_commit();
    ISSUE_PLANE(2, 2); cp_commit();

#define STEP(I)                                                               \
    do {                                                                      \
        cp_wait2();                                                           \
        __syncthreads();                                                      \
        if ((I) + 3 < NP) ISSUE_PLANE((I) + 3, ((I) + 3) % NSTAGE);           \
        cp_commit();                                                          \
        F2 S[2], D[2], W[2];                                                  \
        plane_consume<(I) % NSTAGE>(warp, lane, S, D, W, TWO2, l0, l31);      \
        if ((I) >= 2) {                                                       \
            _Pragma("unroll")                                                 \
            for (int h = 0; h < 2; ++h) {                                     \
                F2 gd = SUB2(S[h], s_old[h]);                                 \
                F2 gh = ADD2(pend_h0[h], D[h]);                               \
                F2 gw = ADD2(pend_w0[h], W[h]);                               \
                acc[h] = ADD2(acc[h], ABS2(gd));                              \
                acc[h] = ADD2(acc[h], ABS2(gh));                              \
                acc[h] = ADD2(acc[h], ABS2(gw));                              \
            }                                                                 \
        }                                                                     \
        _Pragma("unroll")                                                     \
        for (int h = 0; h < 2; ++h) {                                         \
            pend_h0[h] = FMA2(D[h], TWO2, pend_h1[h]);                        \
            pend_h1[h] = D[h];                                                \
            pend_w0[h] = FMA2(W[h], TWO2, pend_w1[h]);                        \
            pend_w1[h] = W[h];                                                \
            s_old[h] = s_new[h];                                              \
            s_new[h] = S[h];                                                  \
        }                                                                     \
    } while (0)

    STEP(0);  STEP(1);  STEP(2);  STEP(3);  STEP(4);  STEP(5);
    STEP(6);  STEP(7);  STEP(8);  STEP(9);  STEP(10); STEP(11);
    STEP(12); STEP(13); STEP(14); STEP(15); STEP(16); STEP(17);

    // ---- block reduction ----
    float ax, ay, az, aw;
    UNPACK2(acc[0], ax, ay);
    UNPACK2(acc[1], az, aw);
    float a = (ax + ay) + (az + aw);
#pragma unroll
    for (int off = 16; off > 0; off >>= 1)
        a += __shfl_down_sync(0xffffffffu, a, off);

    if (lane == 0) wsum_sm[warp] = a;
    __syncthreads();

    __shared__ bool is_last;
    if (tid == 0) {
        float v = 0.f;
#pragma unroll
        for (int w = 0; w < 8; ++w) v += wsum_sm[w];
        g_partials[bid] = v;
        __threadfence();
        unsigned old = atomicAdd(&g_count, 1u);
        is_last = (old == NBLK - 1);
    }
    __syncthreads();

    if (is_last) {
        __threadfence();
        const volatile float* pv = g_partials;
        float s = 0.f;
#pragma unroll
        for (int k = 0; k < NBLK / 256; ++k)
            s += pv[tid + 256 * k];
#pragma unroll
        for (int off = 16; off > 0; off >>= 1)
            s += __shfl_down_sync(0xffffffffu, s, off);
        if (lane == 0) wsum_sm[warp] = s;
        __syncthreads();
        if (tid == 0) {
            float v = 0.f;
#pragma unroll
            for (int w = 0; w < 8; ++w) v += wsum_sm[w];
            out[0] = v * (1.0f / (3.0f * 16.0f * 64.0f * 128.0f * 128.0f));
            g_count = 0;            // reset for next graph replay
        }
    }
}

extern "C" void kernel_launch(void* const* d_in, const int* in_sizes, int n_in,
                              void* d_out, int out_size) {
    const float* pred = (const float*)d_in[0];
    const float* tgt  = (const float*)d_in[1];
    float* out = (float*)d_out;

    dim3 grid(H_DIM / TH, BC_DIM, D_DIM / ZC);   // 16 x 16 x 4 = 1024 blocks
    sg3d_loss_kernel<<<grid, 256>>>(pred, tgt, out);
}

// round 8
// speedup vs baseline: 1.1733x; 1.1733x over previous
#include <cuda_runtime.h>
#include <cstdint>

// SpatialGradientLoss3D = mean |sobel3d(pred - target)| over 3 axes.
// R8: R6 consume math + 4-stage ring, but loads via cp.async.bulk:
// full-W tile => each plane's 10-row halo tile is ONE contiguous 5120B
// region per tensor. One thread issues 2 bulk copies + mbarrier expect_tx
// per plane; consumers wait parity. h-halo rows zeroed once pre-loop;
// z-edge planes consume as zeros. Single launch, last-block reduction.
// Shapes fixed: (B=4, C=4, D=64, H=128, W=128), fp32, out = 1 float.

#define D_DIM 64
#define H_DIM 128
#define W_DIM 128
#define HW    (H_DIM * W_DIM)
#define BC_DIM 16
#define TH 8
#define PR (TH + 2)
#define ZC 16
#define NP (ZC + 2)             // 18 planes touched
#define NSTAGE 4
#define PLANE_F4 (2 * PR * 32)  // 640 float4 per stage (P then T)
#define STAGE_BYTES (PLANE_F4 * 16)   // 10240
#define T_OFF 5120              // T tile byte offset within a stage
#define ROW_BYTES 512
#define NBLK (16 * 16 * 4)      // 1024

typedef unsigned long long F2;  // packed f32x2

__device__ __forceinline__ F2 PACK2(float lo, float hi) {
    F2 r; asm("mov.b64 %0,{%1,%2};" : "=l"(r) : "f"(lo), "f"(hi)); return r;
}
__device__ __forceinline__ void UNPACK2(F2 v, float& lo, float& hi) {
    asm("mov.b64 {%0,%1},%2;" : "=f"(lo), "=f"(hi) : "l"(v));
}
__device__ __forceinline__ F2 ADD2(F2 a, F2 b) {
    F2 r; asm("add.rn.f32x2 %0,%1,%2;" : "=l"(r) : "l"(a), "l"(b)); return r;
}
__device__ __forceinline__ F2 SUB2(F2 a, F2 b) {
    F2 r; asm("sub.rn.f32x2 %0,%1,%2;" : "=l"(r) : "l"(a), "l"(b)); return r;
}
__device__ __forceinline__ F2 FMA2(F2 a, F2 b, F2 c) {
    F2 r; asm("fma.rn.f32x2 %0,%1,%2,%3;" : "=l"(r) : "l"(a), "l"(b), "l"(c)); return r;
}
__device__ __forceinline__ F2 ABS2(F2 a) { return a & 0x7FFFFFFF7FFFFFFFULL; }

// ---- bulk-async + mbarrier primitives ----
__device__ __forceinline__ void mbar_init(uint32_t mbar, int count) {
    asm volatile("mbarrier.init.shared::cta.b64 [%0], %1;" :: "r"(mbar), "r"(count) : "memory");
}
__device__ __forceinline__ void mbar_expect_tx(uint32_t mbar, uint32_t bytes) {
    asm volatile("mbarrier.arrive.expect_tx.shared::cta.b64 _, [%0], %1;"
                 :: "r"(mbar), "r"(bytes) : "memory");
}
__device__ __forceinline__ void mbar_arrive(uint32_t mbar) {
    asm volatile("mbarrier.arrive.shared::cta.b64 _, [%0];" :: "r"(mbar) : "memory");
}
__device__ __forceinline__ void mbar_wait(uint32_t mbar, uint32_t parity) {
    asm volatile(
        "{\n\t"
        ".reg .pred P1;\n\t"
        "WAIT_LOOP_%=:\n\t"
        "mbarrier.try_wait.parity.acquire.cta.shared::cta.b64 P1, [%0], %1, 0x989680;\n\t"
        "@P1 bra.uni WAIT_DONE_%=;\n\t"
        "bra.uni WAIT_LOOP_%=;\n\t"
        "WAIT_DONE_%=:\n\t"
        "}"
        :: "r"(mbar), "r"(parity) : "memory");
}
__device__ __forceinline__ void bulk_g2s(uint32_t dst, const void* src, uint32_t bytes,
                                         uint32_t mbar) {
    asm volatile("cp.async.bulk.shared::cta.global.mbarrier::complete_tx::bytes "
                 "[%0], [%1], %2, [%3];"
                 :: "r"(dst), "l"(src), "r"(bytes), "r"(mbar) : "memory");
}

__shared__ float4 sbuf[NSTAGE][PLANE_F4];
__shared__ unsigned long long mbars[NSTAGE];
__shared__ float wsum_sm[8];

__device__ float g_partials[NBLK];
__device__ unsigned g_count = 0;

// Consume plane from ring stage STG into z-slot SLOT (R6 math, unchanged).
template<int STG, int SLOT>
__device__ __forceinline__ void plane_consume(int warp, int lane,
                                              F2 (*ss)[2], F2 (*ds)[2], F2 (*sd)[2],
                                              F2 TWO2, bool l0, bool l31) {
    const ulonglong2* sb = reinterpret_cast<const ulonglong2*>(&sbuf[STG][0]);
    F2 ws[3][2], wd[3][2];
#pragma unroll
    for (int dr = 0; dr < 3; ++dr) {
        ulonglong2 pv = sb[(warp + dr) * 32 + lane];
        ulonglong2 tv = sb[PR * 32 + (warp + dr) * 32 + lane];
        F2 e01 = SUB2(pv.x, tv.x);
        F2 e23 = SUB2(pv.y, tv.y);
        float e0, e1, e2, e3;
        UNPACK2(e01, e0, e1);
        UNPACK2(e23, e2, e3);
        float eL = __shfl_up_sync(0xffffffffu, e3, 1);
        float eR = __shfl_down_sync(0xffffffffu, e0, 1);
        if (l0)  eL = 0.f;
        if (l31) eR = 0.f;
        F2 pm  = PACK2(eL, e0);
        F2 p12 = PACK2(e1, e2);
        F2 pr  = PACK2(e3, eR);
        ws[dr][0] = ADD2(FMA2(e01, TWO2, pm),  p12);
        ws[dr][1] = ADD2(FMA2(e23, TWO2, p12), pr);
        wd[dr][0] = SUB2(p12, pm);
        wd[dr][1] = SUB2(pr, p12);
    }
#pragma unroll
    for (int h = 0; h < 2; ++h) {
        ss[SLOT][h] = ADD2(FMA2(ws[1][h], TWO2, ws[0][h]), ws[2][h]);
        ds[SLOT][h] = SUB2(ws[2][h], ws[0][h]);
        sd[SLOT][h] = ADD2(FMA2(wd[1][h], TWO2, wd[0][h]), wd[2][h]);
    }
}

template<int SP>
__device__ __forceinline__ void z_combine(const F2 (*ss)[2], const F2 (*ds)[2],
                                          const F2 (*sd)[2], F2* acc, F2 TWO2) {
    constexpr int SM = (SP + 1) % 3;
    constexpr int S0 = (SP + 2) % 3;
#pragma unroll
    for (int h = 0; h < 2; ++h) {
        F2 gd = SUB2(ss[SP][h], ss[SM][h]);
        F2 gh = ADD2(FMA2(ds[S0][h], TWO2, ds[SM][h]), ds[SP][h]);
        F2 gw = ADD2(FMA2(sd[S0][h], TWO2, sd[SM][h]), sd[SP][h]);
        acc[h] = ADD2(acc[h], ABS2(gd));
        acc[h] = ADD2(acc[h], ABS2(gh));
        acc[h] = ADD2(acc[h], ABS2(gw));
    }
}

__global__ __launch_bounds__(256, 3)
void sg3d_loss_kernel(const float* __restrict__ pred,
                      const float* __restrict__ tgt,
                      float* __restrict__ out) {
    const int tid  = threadIdx.x;
    const int lane = tid & 31;
    const int warp = tid >> 5;
    const bool l0  = (lane == 0);
    const bool l31 = (lane == 31);

    const int h0 = blockIdx.x * TH;
    const int bc = blockIdx.y;
    const int z0 = blockIdx.z * ZC;
    const int bid = blockIdx.x + (blockIdx.y << 4) + (blockIdx.z << 8);

    const size_t base = (size_t)bc * D_DIM * HW;
    const float* P = pred + base;
    const float* T = tgt + base;

    uint32_t smem_base, mbar_base;
    asm("{ .reg .u64 t; cvta.to.shared.u64 t, %1; cvt.u32.u64 %0, t; }"
        : "=r"(smem_base) : "l"((const void*)&sbuf[0][0]));
    asm("{ .reg .u64 t; cvta.to.shared.u64 t, %1; cvt.u32.u64 %0, t; }"
        : "=r"(mbar_base) : "l"((const void*)&mbars[0]));

    // ---- tile geometry (uniform per block) ----
    const int row_lo = (h0 == 0) ? 1 : 0;                       // skip top halo row?
    const int row_hi = (h0 == H_DIM - TH) ? 8 : 9;              // skip bottom halo row?
    const uint32_t cp_bytes = (uint32_t)(row_hi - row_lo + 1) * ROW_BYTES;
    const int src_row = h0 - 1 + row_lo;                        // first gmem row copied
    const uint32_t dst_off = (uint32_t)row_lo * ROW_BYTES;
    const bool z_first_ok = (z0 > 0);
    const bool z_last_ok  = (z0 + ZC < D_DIM);

    // ---- init: mbarriers + zero never-written halo rows in all stages ----
    if (tid == 0) {
#pragma unroll
        for (int s = 0; s < NSTAGE; ++s) mbar_init(mbar_base + 8u * s, 1);
    }
    if (row_lo == 1 || row_hi == 8) {
        const int zr = (row_lo == 1) ? 0 : 9;   // the halo row never overwritten
        if (tid < 4 * 2 * 32) {                 // stage, tile, lane
            int s    = tid >> 6;
            int tile = (tid >> 5) & 1;
            int ln   = tid & 31;
            sbuf[s][tile * (PR * 32) + zr * 32 + ln] =
                make_float4(0.f, 0.f, 0.f, 0.f);
        }
    }
    __syncthreads();

    // issue plane J (global z = z0-1+J) into STAGE; VALID = z in range
#define ISSUE_PLANE(J, STAGE, VALID)                                          \
    do {                                                                      \
        if (tid == 0) {                                                       \
            uint32_t mb_ = mbar_base + 8u * (STAGE);                          \
            if (VALID) {                                                      \
                const float* ps_ = P + (size_t)(z0 - 1 + (J)) * HW + src_row * W_DIM; \
                const float* ts_ = T + (size_t)(z0 - 1 + (J)) * HW + src_row * W_DIM; \
                uint32_t d_ = smem_base + (STAGE) * STAGE_BYTES + dst_off;    \
                mbar_expect_tx(mb_, 2 * cp_bytes);                            \
                bulk_g2s(d_, ps_, cp_bytes, mb_);                             \
                bulk_g2s(d_ + T_OFF, ts_, cp_bytes, mb_);                     \
            } else {                                                          \
                mbar_arrive(mb_);                                             \
            }                                                                 \
        }                                                                     \
    } while (0)

    const F2 TWO2 = 0x4000000040000000ULL;
    F2 ss[3][2], ds[3][2], sd[3][2];
    F2 acc[2] = {0ULL, 0ULL};

    // prologue: planes 0,1,2 -> stages 0,1,2
    ISSUE_PLANE(0, 0, z_first_ok);
    ISSUE_PLANE(1, 1, true);
    ISSUE_PLANE(2, 2, true);

    // VALIDC: whether this plane's data is real (else consume zeros)
#define STEP(I, VALIDC)                                                       \
    do {                                                                      \
        constexpr int stg_ = (I) % NSTAGE;                                    \
        constexpr uint32_t par_ = ((I) >> 2) & 1;                             \
        mbar_wait(mbar_base + 8u * stg_, par_);                               \
        if ((I) + 3 < NP) {                                                   \
            ISSUE_PLANE((I) + 3, ((I) + 3) % NSTAGE,                          \
                        ((I) + 3 == NP - 1) ? z_last_ok : true);              \
        }                                                                     \
        if (VALIDC) {                                                         \
            plane_consume<stg_, (I) % 3>(warp, lane, ss, ds, sd,              \
                                         TWO2, l0, l31);                      \
        } else {                                                              \
            _Pragma("unroll")                                                 \
            for (int h = 0; h < 2; ++h) {                                     \
                ss[(I) % 3][h] = 0; ds[(I) % 3][h] = 0; sd[(I) % 3][h] = 0;   \
            }                                                                 \
        }                                                                     \
        if ((I) >= 2) z_combine<(I) % 3>(ss, ds, sd, acc, TWO2);              \
        __syncthreads();                                                      \
    } while (0)

    STEP(0, z_first_ok);
    STEP(1, true);  STEP(2, true);  STEP(3, true);  STEP(4, true);
    STEP(5, true);  STEP(6, true);  STEP(7, true);  STEP(8, true);
    STEP(9, true);  STEP(10, true); STEP(11, true); STEP(12, true);
    STEP(13, true); STEP(14, true); STEP(15, true); STEP(16, true);
    STEP(17, z_last_ok);

    // ---- block reduction ----
    float ax, ay, az, aw;
    UNPACK2(acc[0], ax, ay);
    UNPACK2(acc[1], az, aw);
    float a = (ax + ay) + (az + aw);
#pragma unroll
    for (int off = 16; off > 0; off >>= 1)
        a += __shfl_down_sync(0xffffffffu, a, off);

    if (lane == 0) wsum_sm[warp] = a;
    __syncthreads();

    __shared__ bool is_last;
    if (tid == 0) {
        float v = 0.f;
#pragma unroll
        for (int w = 0; w < 8; ++w) v += wsum_sm[w];
        g_partials[bid] = v;
        __threadfence();
        unsigned old = atomicAdd(&g_count, 1u);
        is_last = (old == NBLK - 1);
    }
    __syncthreads();

    if (is_last) {
        __threadfence();
        const volatile float* pv = g_partials;
        float s = 0.f;
#pragma unroll
        for (int k = 0; k < NBLK / 256; ++k)
            s += pv[tid + 256 * k];
#pragma unroll
        for (int off = 16; off > 0; off >>= 1)
            s += __shfl_down_sync(0xffffffffu, s, off);
        if (lane == 0) wsum_sm[warp] = s;
        __syncthreads();
        if (tid == 0) {
            float v = 0.f;
#pragma unroll
            for (int w = 0; w < 8; ++w) v += wsum_sm[w];
            out[0] = v * (1.0f / (3.0f * 16.0f * 64.0f * 128.0f * 128.0f));
            g_count = 0;            // reset for next graph replay
        }
    }
}

extern "C" void kernel_launch(void* const* d_in, const int* in_sizes, int n_in,
                              void* d_out, int out_size) {
    const float* pred = (const float*)d_in[0];
    const float* tgt  = (const float*)d_in[1];
    float* out = (float*)d_out;

    dim3 grid(H_DIM / TH, BC_DIM, D_DIM / ZC);   // 16 x 16 x 4 = 1024 blocks
    sg3d_loss_kernel<<<grid, 256>>>(pred, tgt, out);
}

// round 9
// speedup vs baseline: 1.2153x; 1.0357x over previous
#include <cuda_runtime.h>
#include <cstdint>

// SpatialGradientLoss3D = mean |sobel3d(pred - target)| over 3 axes.
// R9: R6 math/structure, but 2 planes per barrier: ring of 3 super-stages
// (pair of planes each, dynamic smem 61KB), one wait_group+syncthreads per
// pair (9 total). Load issue: exactly 5 slots/thread/pair, running gmem
// pointers, compile-time sz arrays for z-edges (zero-fill => branchless
// consume). Single launch, last-block reduction.
// Shapes fixed: (B=4, C=4, D=64, H=128, W=128), fp32, out = 1 float.

#define D_DIM 64
#define H_DIM 128
#define W_DIM 128
#define HW    (H_DIM * W_DIM)
#define TH 8
#define PR 10
#define ZC 16
#define NPAIR 9                 // 18 planes = 9 pairs
#define PAIR_F4 1280            // 2 planes * (P,T) * 10 rows * 32 f4
#define SUPER_BYTES (PAIR_F4 * 16)    // 20480
#define DSM_BYTES (3 * SUPER_BYTES)   // 61440
#define NBLK 1024

typedef unsigned long long F2;  // packed f32x2

__device__ __forceinline__ F2 PACK2(float lo, float hi) {
    F2 r; asm("mov.b64 %0,{%1,%2};" : "=l"(r) : "f"(lo), "f"(hi)); return r;
}
__device__ __forceinline__ void UNPACK2(F2 v, float& lo, float& hi) {
    asm("mov.b64 {%0,%1},%2;" : "=f"(lo), "=f"(hi) : "l"(v));
}
__device__ __forceinline__ F2 ADD2(F2 a, F2 b) {
    F2 r; asm("add.rn.f32x2 %0,%1,%2;" : "=l"(r) : "l"(a), "l"(b)); return r;
}
__device__ __forceinline__ F2 SUB2(F2 a, F2 b) {
    F2 r; asm("sub.rn.f32x2 %0,%1,%2;" : "=l"(r) : "l"(a), "l"(b)); return r;
}
__device__ __forceinline__ F2 FMA2(F2 a, F2 b, F2 c) {
    F2 r; asm("fma.rn.f32x2 %0,%1,%2,%3;" : "=l"(r) : "l"(a), "l"(b), "l"(c)); return r;
}
__device__ __forceinline__ F2 ABS2(F2 a) { return a & 0x7FFFFFFF7FFFFFFFULL; }

__device__ __forceinline__ void cpasync16(uint32_t dst, const float* src, int sz) {
    asm volatile("cp.async.cg.shared.global [%0], [%1], 16, %2;\n"
                 :: "r"(dst), "l"(src), "r"(sz) : "memory");
}
__device__ __forceinline__ void cp_commit() {
    asm volatile("cp.async.commit_group;\n" ::: "memory");
}
__device__ __forceinline__ void cp_wait1() {
    asm volatile("cp.async.wait_group 1;\n" ::: "memory");
}

extern __shared__ float4 dsm[];          // 3 super-stages
__shared__ float wsum_sm[8];

__device__ float g_partials[NBLK];
__device__ unsigned g_count = 0;

// Consume one plane at f4 offset BASE into z-slot SLOT (R6 math, unchanged).
template<int BASE, int SLOT>
__device__ __forceinline__ void plane_consume(int warp, int lane,
                                              F2 (*ss)[2], F2 (*ds)[2], F2 (*sd)[2],
                                              F2 TWO2, bool l0, bool l31) {
    const ulonglong2* sb = reinterpret_cast<const ulonglong2*>(dsm);
    F2 ws[3][2], wd[3][2];
#pragma unroll
    for (int dr = 0; dr < 3; ++dr) {
        ulonglong2 pv = sb[BASE + (warp + dr) * 32 + lane];
        ulonglong2 tv = sb[BASE + 320 + (warp + dr) * 32 + lane];
        F2 e01 = SUB2(pv.x, tv.x);
        F2 e23 = SUB2(pv.y, tv.y);
        float e0, e1, e2, e3;
        UNPACK2(e01, e0, e1);
        UNPACK2(e23, e2, e3);
        float eL = __shfl_up_sync(0xffffffffu, e3, 1);
        float eR = __shfl_down_sync(0xffffffffu, e0, 1);
        if (l0)  eL = 0.f;
        if (l31) eR = 0.f;
        F2 pm  = PACK2(eL, e0);
        F2 p12 = PACK2(e1, e2);
        F2 pr  = PACK2(e3, eR);
        ws[dr][0] = ADD2(FMA2(e01, TWO2, pm),  p12);
        ws[dr][1] = ADD2(FMA2(e23, TWO2, p12), pr);
        wd[dr][0] = SUB2(p12, pm);
        wd[dr][1] = SUB2(pr, p12);
    }
#pragma unroll
    for (int h = 0; h < 2; ++h) {
        ss[SLOT][h] = ADD2(FMA2(ws[1][h], TWO2, ws[0][h]), ws[2][h]);
        ds[SLOT][h] = SUB2(ws[2][h], ws[0][h]);
        sd[SLOT][h] = ADD2(FMA2(wd[1][h], TWO2, wd[0][h]), wd[2][h]);
    }
}

template<int SP>
__device__ __forceinline__ void z_combine(const F2 (*ss)[2], const F2 (*ds)[2],
                                          const F2 (*sd)[2], F2* acc, F2 TWO2) {
    constexpr int SM = (SP + 1) % 3;
    constexpr int S0 = (SP + 2) % 3;
#pragma unroll
    for (int h = 0; h < 2; ++h) {
        F2 gd = SUB2(ss[SP][h], ss[SM][h]);
        F2 gh = ADD2(FMA2(ds[S0][h], TWO2, ds[SM][h]), ds[SP][h]);
        F2 gw = ADD2(FMA2(sd[S0][h], TWO2, sd[SM][h]), sd[SP][h]);
        acc[h] = ADD2(acc[h], ABS2(gd));
        acc[h] = ADD2(acc[h], ABS2(gh));
        acc[h] = ADD2(acc[h], ABS2(gw));
    }
}

__global__ __launch_bounds__(256, 3)
void sg3d_loss_kernel(const float* __restrict__ pred,
                      const float* __restrict__ tgt,
                      float* __restrict__ out) {
    const int tid  = threadIdx.x;
    const int lane = tid & 31;
    const int warp = tid >> 5;
    const bool l0  = (lane == 0);
    const bool l31 = (lane == 31);

    const int h0 = blockIdx.x * TH;
    const int bc = blockIdx.y;
    const int z0 = blockIdx.z * ZC;
    const int bid = blockIdx.x + (blockIdx.y << 4) + (blockIdx.z << 8);

    const size_t base = (size_t)bc * D_DIM * HW;
    const float* P = pred + base;
    const float* T = tgt + base;

    uint32_t smem_base;
    asm("{ .reg .u64 t; cvta.to.shared.u64 t, %1; cvt.u32.u64 %0, t; }"
        : "=r"(smem_base) : "l"((const void*)&dsm[0]));

    // ---- per-slot hoisted params: pair = 1280 f4, slot k covers tid+256k ----
    const float* gptr[5];
    uint32_t saddr[5];
    int szb[5], sz_first[5], sz_last[5];
#pragma unroll
    for (int k = 0; k < 5; ++k) {
        int idx  = tid + 256 * k;           // [0,1280)
        int a2   = idx >= 640;              // plane-of-pair
        int rel  = idx - a2 * 640;
        int tsel = rel >= 320;              // 0=P, 1=T
        int rel2 = rel - tsel * 320;
        int row  = rel2 >> 5;
        int c4   = rel2 & 31;
        int gh   = h0 - 1 + row;
        int rowok = (unsigned)gh < (unsigned)H_DIM;
        int soff = (rowok ? gh : 0) * W_DIM + c4 * 4;
        // base plane for pair 0 is z0-1 (+a2). May be "plane -1" for z0==0,
        // but that slot's pair-0 copy has sz=0 (no global read).
        gptr[k] = (tsel ? T : P) + (ptrdiff_t)(z0 - 1 + a2) * HW + soff;
        saddr[k] = smem_base + (uint32_t)idx * 16u;
        szb[k]      = rowok ? 16 : 0;
        sz_first[k] = (z0 == 0 && a2 == 0) ? 0 : szb[k];
        sz_last[k]  = (z0 + ZC == D_DIM && a2 == 1) ? 0 : szb[k];
    }

#define ISSUE_PAIR(SUPER, SZ)                                                 \
    do {                                                                      \
        _Pragma("unroll")                                                     \
        for (int k = 0; k < 5; ++k) {                                         \
            cpasync16(saddr[k] + (SUPER) * SUPER_BYTES, gptr[k], SZ[k]);      \
            gptr[k] += 2 * HW;                                                \
        }                                                                     \
    } while (0)

    const F2 TWO2 = 0x4000000040000000ULL;
    F2 ss[3][2], ds[3][2], sd[3][2];
    F2 acc[2] = {0ULL, 0ULL};

    // prologue: pairs 0,1 -> supers 0,1
    ISSUE_PAIR(0, sz_first); cp_commit();
    ISSUE_PAIR(1, szb);      cp_commit();

    // step S: wait pair S, sync, issue pair S+2 into super (S+2)%3,
    // consume planes 2S, 2S+1 from super S%3.
#define STEP(S, DO_ISSUE, SZ)                                                 \
    do {                                                                      \
        cp_wait1();                                                           \
        __syncthreads();                                                      \
        if (DO_ISSUE) { ISSUE_PAIR(((S) + 2) % 3, SZ); }                      \
        cp_commit();                                                          \
        plane_consume<((S) % 3) * PAIR_F4, (2 * (S)) % 3>(                    \
            warp, lane, ss, ds, sd, TWO2, l0, l31);                           \
        if (2 * (S) >= 2) z_combine<(2 * (S)) % 3>(ss, ds, sd, acc, TWO2);    \
        plane_consume<((S) % 3) * PAIR_F4 + 640, (2 * (S) + 1) % 3>(          \
            warp, lane, ss, ds, sd, TWO2, l0, l31);                           \
        if (2 * (S) + 1 >= 2) z_combine<(2 * (S) + 1) % 3>(ss, ds, sd,        \
                                                           acc, TWO2);        \
    } while (0)

    STEP(0, 1, szb);
    STEP(1, 1, szb);
    STEP(2, 1, szb);
    STEP(3, 1, szb);
    STEP(4, 1, szb);
    STEP(5, 1, szb);
    STEP(6, 1, sz_last);
    STEP(7, 0, szb);
    STEP(8, 0, szb);

    // ---- block reduction ----
    float ax, ay, az, aw;
    UNPACK2(acc[0], ax, ay);
    UNPACK2(acc[1], az, aw);
    float a = (ax + ay) + (az + aw);
#pragma unroll
    for (int off = 16; off > 0; off >>= 1)
        a += __shfl_down_sync(0xffffffffu, a, off);

    if (lane == 0) wsum_sm[warp] = a;
    __syncthreads();

    __shared__ bool is_last;
    if (tid == 0) {
        float v = 0.f;
#pragma unroll
        for (int w = 0; w < 8; ++w) v += wsum_sm[w];
        g_partials[bid] = v;
        __threadfence();
        unsigned old = atomicAdd(&g_count, 1u);
        is_last = (old == NBLK - 1);
    }
    __syncthreads();

    if (is_last) {
        __threadfence();
        const volatile float* pv = g_partials;
        float s = 0.f;
#pragma unroll
        for (int k = 0; k < NBLK / 256; ++k)
            s += pv[tid + 256 * k];
#pragma unroll
        for (int off = 16; off > 0; off >>= 1)
            s += __shfl_down_sync(0xffffffffu, s, off);
        if (lane == 0) wsum_sm[warp] = s;
        __syncthreads();
        if (tid == 0) {
            float v = 0.f;
#pragma unroll
            for (int w = 0; w < 8; ++w) v += wsum_sm[w];
            out[0] = v * (1.0f / (3.0f * 16.0f * 64.0f * 128.0f * 128.0f));
            g_count = 0;            // reset for next graph replay
        }
    }
}

extern "C" void kernel_launch(void* const* d_in, const int* in_sizes, int n_in,
                              void* d_out, int out_size) {
    const float* pred = (const float*)d_in[0];
    const float* tgt  = (const float*)d_in[1];
    float* out = (float*)d_out;

    cudaFuncSetAttribute(sg3d_loss_kernel,
                         cudaFuncAttributeMaxDynamicSharedMemorySize, DSM_BYTES);

    dim3 grid(H_DIM / TH, 16, D_DIM / ZC);   // 16 x 16 x 4 = 1024 blocks
    sg3d_loss_kernel<<<grid, 256, DSM_BYTES>>>(pred, tgt, out);
}

// round 11
// speedup vs baseline: 1.3551x; 1.1150x over previous
#include <cuda_runtime.h>
#include <cstdint>

// SpatialGradientLoss3D = mean |sobel3d(pred - target)| over 3 axes.
// R10b: R6 (best, 33.5us) + stall surgery (fixed macro bug from R10):
//  - NSTAGE=6 ring (61KB dynamic smem), prefetch depth 4
//  - issue-before-wait step order; WAR safe via sync(I-1) covering consume(I-2)
//  - running gmem pointers + precomputed per-slot copy sizes
// Consume math, slot layout, reduction identical to R6.
// Shapes fixed: (B=4, C=4, D=64, H=128, W=128), fp32, out = 1 float.

#define D_DIM 64
#define H_DIM 128
#define W_DIM 128
#define HW    (H_DIM * W_DIM)
#define TH 8
#define PR 10
#define ZC 16
#define NP 18                   // planes touched per block
#define NSTAGE 6
#define PLANE_F4 640            // (P,T) * 10 rows * 32 f4
#define STAGE_BYTES (PLANE_F4 * 16)       // 10240
#define DSM_BYTES (NSTAGE * STAGE_BYTES)  // 61440
#define NBLK 1024

typedef unsigned long long F2;  // packed f32x2

__device__ __forceinline__ F2 PACK2(float lo, float hi) {
    F2 r; asm("mov.b64 %0,{%1,%2};" : "=l"(r) : "f"(lo), "f"(hi)); return r;
}
__device__ __forceinline__ void UNPACK2(F2 v, float& lo, float& hi) {
    asm("mov.b64 {%0,%1},%2;" : "=f"(lo), "=f"(hi) : "l"(v));
}
__device__ __forceinline__ F2 ADD2(F2 a, F2 b) {
    F2 r; asm("add.rn.f32x2 %0,%1,%2;" : "=l"(r) : "l"(a), "l"(b)); return r;
}
__device__ __forceinline__ F2 SUB2(F2 a, F2 b) {
    F2 r; asm("sub.rn.f32x2 %0,%1,%2;" : "=l"(r) : "l"(a), "l"(b)); return r;
}
__device__ __forceinline__ F2 FMA2(F2 a, F2 b, F2 c) {
    F2 r; asm("fma.rn.f32x2 %0,%1,%2,%3;" : "=l"(r) : "l"(a), "l"(b), "l"(c)); return r;
}
__device__ __forceinline__ F2 ABS2(F2 a) { return a & 0x7FFFFFFF7FFFFFFFULL; }

__device__ __forceinline__ void cpasync16(uint32_t dst, const float* src, int sz) {
    asm volatile("cp.async.cg.shared.global [%0], [%1], 16, %2;\n"
                 :: "r"(dst), "l"(src), "r"(sz) : "memory");
}
__device__ __forceinline__ void cp_commit() {
    asm volatile("cp.async.commit_group;\n" ::: "memory");
}
__device__ __forceinline__ void cp_wait4() {
    asm volatile("cp.async.wait_group 4;\n" ::: "memory");
}

extern __shared__ float4 dsm[];          // 6-stage ring
__shared__ float wsum_sm[8];

__device__ float g_partials[NBLK];
__device__ unsigned g_count = 0;

// Consume plane from ring stage STG into z-slot SLOT (R6 math, unchanged).
template<int STG, int SLOT>
__device__ __forceinline__ void plane_consume(int warp, int lane,
                                              F2 (*ss)[2], F2 (*ds)[2], F2 (*sd)[2],
                                              F2 TWO2, bool l0, bool l31) {
    const ulonglong2* sb =
        reinterpret_cast<const ulonglong2*>(dsm) + STG * PLANE_F4;
    F2 ws[3][2], wd[3][2];
#pragma unroll
    for (int dr = 0; dr < 3; ++dr) {
        ulonglong2 pv = sb[(warp + dr) * 32 + lane];
        ulonglong2 tv = sb[PR * 32 + (warp + dr) * 32 + lane];
        F2 e01 = SUB2(pv.x, tv.x);
        F2 e23 = SUB2(pv.y, tv.y);
        float e0, e1, e2, e3;
        UNPACK2(e01, e0, e1);
        UNPACK2(e23, e2, e3);
        float eL = __shfl_up_sync(0xffffffffu, e3, 1);
        float eR = __shfl_down_sync(0xffffffffu, e0, 1);
        if (l0)  eL = 0.f;
        if (l31) eR = 0.f;
        F2 pm  = PACK2(eL, e0);
        F2 p12 = PACK2(e1, e2);
        F2 pr  = PACK2(e3, eR);
        ws[dr][0] = ADD2(FMA2(e01, TWO2, pm),  p12);
        ws[dr][1] = ADD2(FMA2(e23, TWO2, p12), pr);
        wd[dr][0] = SUB2(p12, pm);
        wd[dr][1] = SUB2(pr, p12);
    }
#pragma unroll
    for (int h = 0; h < 2; ++h) {
        ss[SLOT][h] = ADD2(FMA2(ws[1][h], TWO2, ws[0][h]), ws[2][h]);
        ds[SLOT][h] = SUB2(ws[2][h], ws[0][h]);
        sd[SLOT][h] = ADD2(FMA2(wd[1][h], TWO2, wd[0][h]), wd[2][h]);
    }
}

template<int SP>
__device__ __forceinline__ void z_combine(const F2 (*ss)[2], const F2 (*ds)[2],
                                          const F2 (*sd)[2], F2* acc, F2 TWO2) {
    constexpr int SM = (SP + 1) % 3;
    constexpr int S0 = (SP + 2) % 3;
#pragma unroll
    for (int h = 0; h < 2; ++h) {
        F2 gd = SUB2(ss[SP][h], ss[SM][h]);
        F2 gh = ADD2(FMA2(ds[S0][h], TWO2, ds[SM][h]), ds[SP][h]);
        F2 gw = ADD2(FMA2(sd[S0][h], TWO2, sd[SM][h]), sd[SP][h]);
        acc[h] = ADD2(acc[h], ABS2(gd));
        acc[h] = ADD2(acc[h], ABS2(gh));
        acc[h] = ADD2(acc[h], ABS2(gw));
    }
}

__global__ __launch_bounds__(256, 3)
void sg3d_loss_kernel(const float* __restrict__ pred,
                      const float* __restrict__ tgt,
                      float* __restrict__ out) {
    const int tid  = threadIdx.x;
    const int lane = tid & 31;
    const int warp = tid >> 5;
    const bool l0  = (lane == 0);
    const bool l31 = (lane == 31);

    const int h0 = blockIdx.x * TH;
    const int bc = blockIdx.y;
    const int z0 = blockIdx.z * ZC;
    const int bid = blockIdx.x + (blockIdx.y << 4) + (blockIdx.z << 8);

    const size_t base = (size_t)bc * D_DIM * HW;
    const float* P = pred + base;
    const float* T = tgt + base;

    uint32_t smem_base;
    asm("{ .reg .u64 t; cvta.to.shared.u64 t, %1; cvt.u32.u64 %0, t; }"
        : "=r"(smem_base) : "l"((const void*)&dsm[0]));

    // ---- per-slot hoisted params; slot k covers idx = tid + 256k, idx<640 ----
    const float* gptr[3];
    uint32_t saddr[3];
    int szb[3], szf[3], szl[3];
    const bool act2 = (tid < PLANE_F4 - 512);   // slot 2 valid for tid<128
    const bool zf = (z0 == 0);
    const bool zl = (z0 + ZC == D_DIM);
#pragma unroll
    for (int k = 0; k < 3; ++k) {
        int idx = tid + 256 * k;
        if (idx >= PLANE_F4) idx = PLANE_F4 - 1;    // inert for inactive slot 2
        int a   = idx >= PR * 32;                   // 0=P tile, 1=T tile
        int rel = idx - a * PR * 32;
        int row = rel >> 5;
        int c4  = rel & 31;
        int gh  = h0 - 1 + row;
        int rowok = (unsigned)gh < (unsigned)H_DIM;
        int soff = (rowok ? gh : 0) * W_DIM + c4 * 4;
        gptr[k] = (a ? T : P) + (ptrdiff_t)(z0 - 1) * HW + soff;
        saddr[k] = smem_base + (uint32_t)idx * 16u;
        szb[k] = rowok ? 16 : 0;
        szf[k] = zf ? 0 : szb[k];
        szl[k] = zl ? 0 : szb[k];
    }

#define ISSUE_PLANE(STAGE, SZ)                                                \
    do {                                                                      \
        cpasync16(saddr[0] + (STAGE) * STAGE_BYTES, gptr[0], (SZ)[0]);        \
        cpasync16(saddr[1] + (STAGE) * STAGE_BYTES, gptr[1], (SZ)[1]);        \
        if (act2)                                                             \
            cpasync16(saddr[2] + (STAGE) * STAGE_BYTES, gptr[2], (SZ)[2]);    \
        gptr[0] += HW; gptr[1] += HW; gptr[2] += HW;                          \
    } while (0)

    const F2 TWO2 = 0x4000000040000000ULL;
    F2 ss[3][2], ds[3][2], sd[3][2];
    F2 acc[2] = {0ULL, 0ULL};

    // prologue: planes 0..3 -> stages 0..3
    ISSUE_PLANE(0, szf); cp_commit();
    ISSUE_PLANE(1, szb); cp_commit();
    ISSUE_PLANE(2, szb); cp_commit();
    ISSUE_PLANE(3, szb); cp_commit();

    // step I: issue plane I+4 (stage (I+4)%6), commit, wait_group(4) ->
    // plane I arrived, sync, consume plane I.
#define STEP(I)                                                               \
    do {                                                                      \
        if ((I) + 4 < NP) {                                                   \
            const int* sz_ = (((I) + 4) == NP - 1) ? szl : szb;               \
            ISSUE_PLANE(((I) + 4) % NSTAGE, sz_);                             \
        }                                                                     \
        cp_commit();                                                          \
        cp_wait4();                                                           \
        __syncthreads();                                                      \
        plane_consume<(I) % NSTAGE, (I) % 3>(warp, lane, ss, ds, sd,          \
                                             TWO2, l0, l31);                  \
        if ((I) >= 2) z_combine<(I) % 3>(ss, ds, sd, acc, TWO2);              \
    } while (0)

    STEP(0);  STEP(1);  STEP(2);  STEP(3);  STEP(4);  STEP(5);
    STEP(6);  STEP(7);  STEP(8);  STEP(9);  STEP(10); STEP(11);
    STEP(12); STEP(13); STEP(14); STEP(15); STEP(16); STEP(17);

    // ---- block reduction ----
    float ax, ay, az, aw;
    UNPACK2(acc[0], ax, ay);
    UNPACK2(acc[1], az, aw);
    float a = (ax + ay) + (az + aw);
#pragma unroll
    for (int off = 16; off > 0; off >>= 1)
        a += __shfl_down_sync(0xffffffffu, a, off);

    if (lane == 0) wsum_sm[warp] = a;
    __syncthreads();

    __shared__ bool is_last;
    if (tid == 0) {
        float v = 0.f;
#pragma unroll
        for (int w = 0; w < 8; ++w) v += wsum_sm[w];
        g_partials[bid] = v;
        __threadfence();
        unsigned old = atomicAdd(&g_count, 1u);
        is_last = (old == NBLK - 1);
    }
    __syncthreads();

    if (is_last) {
        __threadfence();
        const volatile float* pv = g_partials;
        float s = 0.f;
#pragma unroll
        for (int k = 0; k < NBLK / 256; ++k)
            s += pv[tid + 256 * k];
#pragma unroll
        for (int off = 16; off > 0; off >>= 1)
            s += __shfl_down_sync(0xffffffffu, s, off);
        if (lane == 0) wsum_sm[warp] = s;
        __syncthreads();
        if (tid == 0) {
            float v = 0.f;
#pragma unroll
            for (int w = 0; w < 8; ++w) v += wsum_sm[w];
            out[0] = v * (1.0f / (3.0f * 16.0f * 64.0f * 128.0f * 128.0f));
            g_count = 0;            // reset for next graph replay
        }
    }
}

extern "C" void kernel_launch(void* const* d_in, const int* in_sizes, int n_in,
                              void* d_out, int out_size) {
    const float* pred = (const float*)d_in[0];
    const float* tgt  = (const float*)d_in[1];
    float* out = (float*)d_out;

    cudaFuncSetAttribute(sg3d_loss_kernel,
                         cudaFuncAttributeMaxDynamicSharedMemorySize, DSM_BYTES);

    dim3 grid(H_DIM / TH, 16, D_DIM / ZC);   // 16 x 16 x 4 = 1024 blocks
    sg3d_loss_kernel<<<grid, 256, DSM_BYTES>>>(pred, tgt, out);
}

// round 12
// speedup vs baseline: 1.4385x; 1.0615x over previous
#include <cuda_runtime.h>
#include <cstdint>

// SpatialGradientLoss3D = mean |sobel3d(pred - target)| over 3 axes.
// R12: R6 (best, 33.5us) byte-identical pipeline with ONE change:
// __launch_bounds__(256,4) (occupancy 3->4 CTAs/SM) + affine saddr
// (slot address = saddr0 + k*4096, compile-time) to relieve reg pressure.
// 4-stage cp.async ring, depth-3 prefetch, wait_group 2, f32x2 consume,
// single launch with last-block reduction.
// Shapes fixed: (B=4, C=4, D=64, H=128, W=128), fp32, out = 1 float.

#define D_DIM 64
#define H_DIM 128
#define W_DIM 128
#define HW    (H_DIM * W_DIM)
#define TH 8
#define PR 10
#define ZC 16
#define NP 18                   // planes touched per block
#define NSTAGE 4
#define PLANE_F4 640            // (P,T) * 10 rows * 32 f4
#define STAGE_BYTES (PLANE_F4 * 16)   // 10240
#define NBLK 1024

typedef unsigned long long F2;  // packed f32x2

__device__ __forceinline__ F2 PACK2(float lo, float hi) {
    F2 r; asm("mov.b64 %0,{%1,%2};" : "=l"(r) : "f"(lo), "f"(hi)); return r;
}
__device__ __forceinline__ void UNPACK2(F2 v, float& lo, float& hi) {
    asm("mov.b64 {%0,%1},%2;" : "=f"(lo), "=f"(hi) : "l"(v));
}
__device__ __forceinline__ F2 ADD2(F2 a, F2 b) {
    F2 r; asm("add.rn.f32x2 %0,%1,%2;" : "=l"(r) : "l"(a), "l"(b)); return r;
}
__device__ __forceinline__ F2 SUB2(F2 a, F2 b) {
    F2 r; asm("sub.rn.f32x2 %0,%1,%2;" : "=l"(r) : "l"(a), "l"(b)); return r;
}
__device__ __forceinline__ F2 FMA2(F2 a, F2 b, F2 c) {
    F2 r; asm("fma.rn.f32x2 %0,%1,%2,%3;" : "=l"(r) : "l"(a), "l"(b), "l"(c)); return r;
}
__device__ __forceinline__ F2 ABS2(F2 a) { return a & 0x7FFFFFFF7FFFFFFFULL; }

__device__ __forceinline__ void cpasync16(uint32_t dst, const float* src, int sz) {
    asm volatile("cp.async.cg.shared.global [%0], [%1], 16, %2;\n"
                 :: "r"(dst), "l"(src), "r"(sz) : "memory");
}
__device__ __forceinline__ void cp_commit() {
    asm volatile("cp.async.commit_group;\n" ::: "memory");
}
__device__ __forceinline__ void cp_wait2() {
    asm volatile("cp.async.wait_group 2;\n" ::: "memory");
}

__shared__ float4 sbuf[NSTAGE][PLANE_F4];
__shared__ float wsum_sm[8];

__device__ float g_partials[NBLK];
__device__ unsigned g_count = 0;

// Consume plane from ring stage STG into z-slot SLOT (R6 math, unchanged).
template<int STG, int SLOT>
__device__ __forceinline__ void plane_consume(int warp, int lane,
                                              F2 (*ss)[2], F2 (*ds)[2], F2 (*sd)[2],
                                              F2 TWO2, bool l0, bool l31) {
    const ulonglong2* sb = reinterpret_cast<const ulonglong2*>(&sbuf[STG][0]);
    F2 ws[3][2], wd[3][2];
#pragma unroll
    for (int dr = 0; dr < 3; ++dr) {
        ulonglong2 pv = sb[(warp + dr) * 32 + lane];
        ulonglong2 tv = sb[PR * 32 + (warp + dr) * 32 + lane];
        F2 e01 = SUB2(pv.x, tv.x);
        F2 e23 = SUB2(pv.y, tv.y);
        float e0, e1, e2, e3;
        UNPACK2(e01, e0, e1);
        UNPACK2(e23, e2, e3);
        float eL = __shfl_up_sync(0xffffffffu, e3, 1);
        float eR = __shfl_down_sync(0xffffffffu, e0, 1);
        if (l0)  eL = 0.f;
        if (l31) eR = 0.f;
        F2 pm  = PACK2(eL, e0);
        F2 p12 = PACK2(e1, e2);
        F2 pr  = PACK2(e3, eR);
        ws[dr][0] = ADD2(FMA2(e01, TWO2, pm),  p12);
        ws[dr][1] = ADD2(FMA2(e23, TWO2, p12), pr);
        wd[dr][0] = SUB2(p12, pm);
        wd[dr][1] = SUB2(pr, p12);
    }
#pragma unroll
    for (int h = 0; h < 2; ++h) {
        ss[SLOT][h] = ADD2(FMA2(ws[1][h], TWO2, ws[0][h]), ws[2][h]);
        ds[SLOT][h] = SUB2(ws[2][h], ws[0][h]);
        sd[SLOT][h] = ADD2(FMA2(wd[1][h], TWO2, wd[0][h]), wd[2][h]);
    }
}

template<int SP>
__device__ __forceinline__ void z_combine(const F2 (*ss)[2], const F2 (*ds)[2],
                                          const F2 (*sd)[2], F2* acc, F2 TWO2) {
    constexpr int SM = (SP + 1) % 3;
    constexpr int S0 = (SP + 2) % 3;
#pragma unroll
    for (int h = 0; h < 2; ++h) {
        F2 gd = SUB2(ss[SP][h], ss[SM][h]);
        F2 gh = ADD2(FMA2(ds[S0][h], TWO2, ds[SM][h]), ds[SP][h]);
        F2 gw = ADD2(FMA2(sd[S0][h], TWO2, sd[SM][h]), sd[SP][h]);
        acc[h] = ADD2(acc[h], ABS2(gd));
        acc[h] = ADD2(acc[h], ABS2(gh));
        acc[h] = ADD2(acc[h], ABS2(gw));
    }
}

__global__ __launch_bounds__(256, 4)
void sg3d_loss_kernel(const float* __restrict__ pred,
                      const float* __restrict__ tgt,
                      float* __restrict__ out) {
    const int tid  = threadIdx.x;
    const int lane = tid & 31;
    const int warp = tid >> 5;
    const bool l0  = (lane == 0);
    const bool l31 = (lane == 31);

    const int h0 = blockIdx.x * TH;
    const int bc = blockIdx.y;
    const int z0 = blockIdx.z * ZC;
    const int bid = blockIdx.x + (blockIdx.y << 4) + (blockIdx.z << 8);

    const size_t base = (size_t)bc * D_DIM * HW;
    const float* P = pred + base;
    const float* T = tgt + base;

    uint32_t smem_base;
    asm("{ .reg .u64 t; cvta.to.shared.u64 t, %1; cvt.u32.u64 %0, t; }"
        : "=r"(smem_base) : "l"((const void*)&sbuf[0][0]));

    // per-slot cp.async params (slot k covers idx = tid + 256k).
    // saddr is affine in k: saddr0 + k*4096 (compile-time in unrolled code).
    const float* gp[3];
    int rowok[3], active[3];
    const uint32_t saddr0 = smem_base + (uint32_t)tid * 16u;
#pragma unroll
    for (int k = 0; k < 3; ++k) {
        int idx = tid + 256 * k;
        active[k] = idx < PLANE_F4;
        int a   = idx >= PR * 32;
        int rel = idx - a * PR * 32;
        int row = rel >> 5;
        int c4  = rel & 31;
        int gh  = h0 - 1 + row;
        rowok[k] = (unsigned)gh < (unsigned)H_DIM;
        int soff = (rowok[k] ? gh : 0) * W_DIM + c4 * 4;
        gp[k] = (a ? T : P) + soff;
    }

#define ISSUE_PLANE(J, STAGE)                                                 \
    do {                                                                      \
        int gz_ = z0 - 1 + (J);                                               \
        int zok_ = (unsigned)gz_ < (unsigned)D_DIM;                           \
        int gzc_ = zok_ ? gz_ : 0;                                            \
        _Pragma("unroll")                                                     \
        for (int k = 0; k < 3; ++k) {                                         \
            if (active[k]) {                                                  \
                int sz_ = (rowok[k] & zok_) ? 16 : 0;                         \
                cpasync16(saddr0 + (uint32_t)(k * 4096) +                     \
                              (STAGE) * STAGE_BYTES,                          \
                          gp[k] + (size_t)gzc_ * HW, sz_);                    \
            }                                                                 \
        }                                                                     \
    } while (0)

    const F2 TWO2 = 0x4000000040000000ULL;
    F2 ss[3][2], ds[3][2], sd[3][2];
    F2 acc[2] = {0ULL, 0ULL};

    // prologue: planes 0,1,2 -> stages 0,1,2
    ISSUE_PLANE(0, 0); cp_commit();
    ISSUE_PLANE(1, 1); cp_commit();
    ISSUE_PLANE(2, 2); cp_commit();

#define STEP(I)                                                               \
    do {                                                                      \
        cp_wait2();                                                           \
        __syncthreads();                                                      \
        if ((I) + 3 < NP) ISSUE_PLANE((I) + 3, ((I) + 3) % NSTAGE);           \
        cp_commit();                                                          \
        plane_consume<(I) % NSTAGE, (I) % 3>(warp, lane, ss, ds, sd,          \
                                             TWO2, l0, l31);                  \
        if ((I) >= 2) z_combine<(I) % 3>(ss, ds, sd, acc, TWO2);              \
    } while (0)

    STEP(0);  STEP(1);  STEP(2);  STEP(3);  STEP(4);  STEP(5);
    STEP(6);  STEP(7);  STEP(8);  STEP(9);  STEP(10); STEP(11);
    STEP(12); STEP(13); STEP(14); STEP(15); STEP(16); STEP(17);

    // ---- block reduction ----
    float ax, ay, az, aw;
    UNPACK2(acc[0], ax, ay);
    UNPACK2(acc[1], az, aw);
    float a = (ax + ay) + (az + aw);
#pragma unroll
    for (int off = 16; off > 0; off >>= 1)
        a += __shfl_down_sync(0xffffffffu, a, off);

    if (lane == 0) wsum_sm[warp] = a;
    __syncthreads();

    __shared__ bool is_last;
    if (tid == 0) {
        float v = 0.f;
#pragma unroll
        for (int w = 0; w < 8; ++w) v += wsum_sm[w];
        g_partials[bid] = v;
        __threadfence();
        unsigned old = atomicAdd(&g_count, 1u);
        is_last = (old == NBLK - 1);
    }
    __syncthreads();

    if (is_last) {
        __threadfence();
        const volatile float* pv = g_partials;
        float s = 0.f;
#pragma unroll
        for (int k = 0; k < NBLK / 256; ++k)
            s += pv[tid + 256 * k];
#pragma unroll
        for (int off = 16; off > 0; off >>= 1)
            s += __shfl_down_sync(0xffffffffu, s, off);
        if (lane == 0) wsum_sm[warp] = s;
        __syncthreads();
        if (tid == 0) {
            float v = 0.f;
#pragma unroll
            for (int w = 0; w < 8; ++w) v += wsum_sm[w];
            out[0] = v * (1.0f / (3.0f * 16.0f * 64.0f * 128.0f * 128.0f));
            g_count = 0;            // reset for next graph replay
        }
    }
}

extern "C" void kernel_launch(void* const* d_in, const int* in_sizes, int n_in,
                              void* d_out, int out_size) {
    const float* pred = (const float*)d_in[0];
    const float* tgt  = (const float*)d_in[1];
    float* out = (float*)d_out;

    dim3 grid(H_DIM / TH, 16, D_DIM / ZC);   // 16 x 16 x 4 = 1024 blocks
    sg3d_loss_kernel<<<grid, 256>>>(pred, tgt, out);
}

// round 13
// speedup vs baseline: 1.6368x; 1.1379x over previous
#include <cuda_runtime.h>
#include <cstdint>

// SpatialGradientLoss3D = mean |sobel3d(pred - target)| over 3 axes.
// R13: R12 pipeline (4-stage cp.async ring, wait_group 2, occ4, single
// launch) with:
//  - h-then-w separable consume: h-conv (hs/hd) straight from row loads
//    (aligned, no packing), w-stage ONCE on hs/hd (was 3x per-row w-conv).
//    Packed ops 30->22, shfl 6->4, pack-movs ~18->~12 per plane.
//  - running gmem pointers + size-mask z-edges (no per-issue z*HW/clamps).
//  - compile-time slot guards (slot2 iff tid<128).
// Shapes fixed: (B=4, C=4, D=64, H=128, W=128), fp32, out = 1 float.

#define D_DIM 64
#define H_DIM 128
#define W_DIM 128
#define HW    (H_DIM * W_DIM)
#define TH 8
#define PR 10
#define ZC 16
#define NP 18                   // planes touched per block
#define NSTAGE 4
#define PLANE_F4 640            // (P,T) * 10 rows * 32 f4
#define STAGE_BYTES (PLANE_F4 * 16)   // 10240
#define NBLK 1024

typedef unsigned long long F2;  // packed f32x2

__device__ __forceinline__ F2 PACK2(float lo, float hi) {
    F2 r; asm("mov.b64 %0,{%1,%2};" : "=l"(r) : "f"(lo), "f"(hi)); return r;
}
__device__ __forceinline__ void UNPACK2(F2 v, float& lo, float& hi) {
    asm("mov.b64 {%0,%1},%2;" : "=f"(lo), "=f"(hi) : "l"(v));
}
__device__ __forceinline__ F2 ADD2(F2 a, F2 b) {
    F2 r; asm("add.rn.f32x2 %0,%1,%2;" : "=l"(r) : "l"(a), "l"(b)); return r;
}
__device__ __forceinline__ F2 SUB2(F2 a, F2 b) {
    F2 r; asm("sub.rn.f32x2 %0,%1,%2;" : "=l"(r) : "l"(a), "l"(b)); return r;
}
__device__ __forceinline__ F2 FMA2(F2 a, F2 b, F2 c) {
    F2 r; asm("fma.rn.f32x2 %0,%1,%2,%3;" : "=l"(r) : "l"(a), "l"(b), "l"(c)); return r;
}
__device__ __forceinline__ F2 ABS2(F2 a) { return a & 0x7FFFFFFF7FFFFFFFULL; }

__device__ __forceinline__ void cpasync16(uint32_t dst, const float* src, int sz) {
    asm volatile("cp.async.cg.shared.global [%0], [%1], 16, %2;\n"
                 :: "r"(dst), "l"(src), "r"(sz) : "memory");
}
__device__ __forceinline__ void cp_commit() {
    asm volatile("cp.async.commit_group;\n" ::: "memory");
}
__device__ __forceinline__ void cp_wait2() {
    asm volatile("cp.async.wait_group 2;\n" ::: "memory");
}

__shared__ float4 sbuf[NSTAGE][PLANE_F4];
__shared__ float wsum_sm[8];

__device__ float g_partials[NBLK];
__device__ unsigned g_count = 0;

// h-then-w consume: plane from ring stage STG into z-slot SLOT.
// ss = smooth_w(smooth_h(e))  -> gd channel (z-deriv)
// ds = smooth_w(deriv_h(e))   -> gh channel (z-smooth)
// sd = deriv_w(smooth_h(e))   -> gw channel (z-smooth)
template<int STG, int SLOT>
__device__ __forceinline__ void plane_consume(int warp, int lane,
                                              F2 (*ss)[2], F2 (*ds)[2], F2 (*sd)[2],
                                              F2 TWO2, bool l0, bool l31) {
    const ulonglong2* sb = reinterpret_cast<const ulonglong2*>(&sbuf[STG][0]);
    F2 e[3][2];
#pragma unroll
    for (int dr = 0; dr < 3; ++dr) {
        ulonglong2 pv = sb[(warp + dr) * 32 + lane];
        ulonglong2 tv = sb[PR * 32 + (warp + dr) * 32 + lane];
        e[dr][0] = SUB2(pv.x, tv.x);
        e[dr][1] = SUB2(pv.y, tv.y);
    }
    F2 hs[2], hd[2];
#pragma unroll
    for (int h = 0; h < 2; ++h) {
        hs[h] = ADD2(FMA2(e[1][h], TWO2, e[0][h]), e[2][h]);
        hd[h] = SUB2(e[2][h], e[0][h]);
    }
    // w-stage on hs
    {
        float s0, s1, s2, s3;
        UNPACK2(hs[0], s0, s1);
        UNPACK2(hs[1], s2, s3);
        float sL = __shfl_up_sync(0xffffffffu, s3, 1);
        float sR = __shfl_down_sync(0xffffffffu, s0, 1);
        if (l0)  sL = 0.f;
        if (l31) sR = 0.f;
        F2 pm  = PACK2(sL, s0);
        F2 p12 = PACK2(s1, s2);
        F2 pr  = PACK2(s3, sR);
        ss[SLOT][0] = ADD2(FMA2(hs[0], TWO2, pm),  p12);
        ss[SLOT][1] = ADD2(FMA2(hs[1], TWO2, p12), pr);
        sd[SLOT][0] = SUB2(p12, pm);
        sd[SLOT][1] = SUB2(pr, p12);
    }
    // w-stage on hd
    {
        float d0, d1, d2, d3;
        UNPACK2(hd[0], d0, d1);
        UNPACK2(hd[1], d2, d3);
        float dL = __shfl_up_sync(0xffffffffu, d3, 1);
        float dR = __shfl_down_sync(0xffffffffu, d0, 1);
        if (l0)  dL = 0.f;
        if (l31) dR = 0.f;
        F2 qm  = PACK2(dL, d0);
        F2 q12 = PACK2(d1, d2);
        F2 qr  = PACK2(d3, dR);
        ds[SLOT][0] = ADD2(FMA2(hd[0], TWO2, qm),  q12);
        ds[SLOT][1] = ADD2(FMA2(hd[1], TWO2, q12), qr);
    }
}

template<int SP>
__device__ __forceinline__ void z_combine(const F2 (*ss)[2], const F2 (*ds)[2],
                                          const F2 (*sd)[2], F2* acc, F2 TWO2) {
    constexpr int SM = (SP + 1) % 3;
    constexpr int S0 = (SP + 2) % 3;
#pragma unroll
    for (int h = 0; h < 2; ++h) {
        F2 gd = SUB2(ss[SP][h], ss[SM][h]);
        F2 gh = ADD2(FMA2(ds[S0][h], TWO2, ds[SM][h]), ds[SP][h]);
        F2 gw = ADD2(FMA2(sd[S0][h], TWO2, sd[SM][h]), sd[SP][h]);
        acc[h] = ADD2(acc[h], ABS2(gd));
        acc[h] = ADD2(acc[h], ABS2(gh));
        acc[h] = ADD2(acc[h], ABS2(gw));
    }
}

__global__ __launch_bounds__(256, 4)
void sg3d_loss_kernel(const float* __restrict__ pred,
                      const float* __restrict__ tgt,
                      float* __restrict__ out) {
    const int tid  = threadIdx.x;
    const int lane = tid & 31;
    const int warp = tid >> 5;
    const bool l0  = (lane == 0);
    const bool l31 = (lane == 31);

    const int h0 = blockIdx.x * TH;
    const int bc = blockIdx.y;
    const int z0 = blockIdx.z * ZC;
    const int bid = blockIdx.x + (blockIdx.y << 4) + (blockIdx.z << 8);

    const size_t base = (size_t)bc * D_DIM * HW;
    const float* P = pred + base;
    const float* T = tgt + base;

    uint32_t smem_base;
    asm("{ .reg .u64 t; cvta.to.shared.u64 t, %1; cvt.u32.u64 %0, t; }"
        : "=r"(smem_base) : "l"((const void*)&sbuf[0][0]));

    // ---- per-slot hoisted params; slot k covers idx = tid + 256k ----
    // Running pointers start at plane 0 (global z = z0-1; may point below the
    // tensor for z0==0 — never dereferenced, that plane's sizes are masked 0).
    const float *gp0, *gp1, *gp2;
    int szb0, szb1, szb2;
    const uint32_t saddr0 = smem_base + (uint32_t)tid * 16u;
    {
#pragma unroll
        for (int k = 0; k < 3; ++k) {
            int idx = tid + 256 * k;
            if (idx >= PLANE_F4) idx = PLANE_F4 - 1;   // inert (slot2, tid>=128)
            int a   = idx >= PR * 32;                  // 0=P tile, 1=T tile
            int rel = idx - a * PR * 32;
            int row = rel >> 5;
            int c4  = rel & 31;
            int gh  = h0 - 1 + row;
            int rowok = (unsigned)gh < (unsigned)H_DIM;
            int soff = (rowok ? gh : 0) * W_DIM + c4 * 4;
            const float* p = (a ? T : P) + (ptrdiff_t)(z0 - 1) * HW + soff;
            int sz = rowok ? 16 : 0;
            if (k == 0) { gp0 = p; szb0 = sz; }
            else if (k == 1) { gp1 = p; szb1 = sz; }
            else { gp2 = p; szb2 = sz; }
        }
    }
    const bool act2 = (tid < 128);
    const int zf_ok = (z0 > 0);
    const int zl_ok = (z0 + ZC < D_DIM);

    // OK: runtime 0/1 gate (compile-time 1 for middle planes -> folds away)
#define ISSUE_PLANE(STAGE, OK)                                                \
    do {                                                                      \
        int m_ = (OK) ? ~0 : 0;                                               \
        cpasync16(saddr0 + (STAGE) * STAGE_BYTES,          gp0, szb0 & m_);   \
        cpasync16(saddr0 + 4096u + (STAGE) * STAGE_BYTES,  gp1, szb1 & m_);   \
        if (act2)                                                             \
            cpasync16(saddr0 + 8192u + (STAGE) * STAGE_BYTES, gp2,            \
                      szb2 & m_);                                             \
        gp0 += HW; gp1 += HW; gp2 += HW;                                      \
    } while (0)

    const F2 TWO2 = 0x4000000040000000ULL;
    F2 ss[3][2], ds[3][2], sd[3][2];
    F2 acc[2] = {0ULL, 0ULL};

    // prologue: planes 0,1,2 -> stages 0,1,2
    ISSUE_PLANE(0, zf_ok); cp_commit();
    ISSUE_PLANE(1, 1);     cp_commit();
    ISSUE_PLANE(2, 1);     cp_commit();

#define STEP(I)                                                               \
    do {                                                                      \
        cp_wait2();                                                           \
        __syncthreads();                                                      \
        if ((I) + 3 < NP)                                                     \
            ISSUE_PLANE(((I) + 3) % NSTAGE,                                   \
                        (((I) + 3) == NP - 1) ? zl_ok : 1);                   \
        cp_commit();                                                          \
        plane_consume<(I) % NSTAGE, (I) % 3>(warp, lane, ss, ds, sd,          \
                                             TWO2, l0, l31);                  \
        if ((I) >= 2) z_combine<(I) % 3>(ss, ds, sd, acc, TWO2);              \
    } while (0)

    STEP(0);  STEP(1);  STEP(2);  STEP(3);  STEP(4);  STEP(5);
    STEP(6);  STEP(7);  STEP(8);  STEP(9);  STEP(10); STEP(11);
    STEP(12); STEP(13); STEP(14); STEP(15); STEP(16); STEP(17);

    // ---- block reduction ----
    float ax, ay, az, aw;
    UNPACK2(acc[0], ax, ay);
    UNPACK2(acc[1], az, aw);
    float a = (ax + ay) + (az + aw);
#pragma unroll
    for (int off = 16; off > 0; off >>= 1)
        a += __shfl_down_sync(0xffffffffu, a, off);

    if (lane == 0) wsum_sm[warp] = a;
    __syncthreads();

    __shared__ bool is_last;
    if (tid == 0) {
        float v = 0.f;
#pragma unroll
        for (int w = 0; w < 8; ++w) v += wsum_sm[w];
        g_partials[bid] = v;
        __threadfence();
        unsigned old = atomicAdd(&g_count, 1u);
        is_last = (old == NBLK - 1);
    }
    __syncthreads();

    if (is_last) {
        __threadfence();
        const volatile float* pv = g_partials;
        float s = 0.f;
#pragma unroll
        for (int k = 0; k < NBLK / 256; ++k)
            s += pv[tid + 256 * k];
#pragma unroll
        for (int off = 16; off > 0; off >>= 1)
            s += __shfl_down_sync(0xffffffffu, s, off);
        if (lane == 0) wsum_sm[warp] = s;
        __syncthreads();
        if (tid == 0) {
            float v = 0.f;
#pragma unroll
            for (int w = 0; w < 8; ++w) v += wsum_sm[w];
            out[0] = v * (1.0f / (3.0f * 16.0f * 64.0f * 128.0f * 128.0f));
            g_count = 0;            // reset for next graph replay
        }
    }
}

extern "C" void kernel_launch(void* const* d_in, const int* in_sizes, int n_in,
                              void* d_out, int out_size) {
    const float* pred = (const float*)d_in[0];
    const float* tgt  = (const float*)d_in[1];
    float* out = (float*)d_out;

    dim3 grid(H_DIM / TH, 16, D_DIM / ZC);   // 16 x 16 x 4 = 1024 blocks
    sg3d_loss_kernel<<<grid, 256>>>(pred, tgt, out);
}